// round 15
// baseline (speedup 1.0000x reference)
#include <cuda_runtime.h>
#include <cuda_fp16.h>
#include <math.h>
#include <stdint.h>

// ---------------------------------------------------------------------------
// TransformerBlock B=4,T=2048,C=1024,NH=16,HD=64,FF=4096 fp32.
// R14: persistent GEMM with CROSS-TILE pipelined cp.async ring (prologue paid
//      once per kernel; epilogue overlaps next tile's loads). R11 flash.
// ---------------------------------------------------------------------------

#define Bsz   4
#define Tlen  2048
#define Cdim  1024
#define NHead 16
#define HDim  64
#define FFdim 4096
#define Mrows (Bsz * Tlen)   // 8192

#define PERSIST_CTAS 296     // 148 SMs * 2 CTAs

// ------------------------- scratch (device globals) ------------------------
__device__ float  g_X1 [Mrows * Cdim];
__device__ __half g_H16  [Mrows * Cdim];
__device__ __half g_QKV16[Mrows * 3 * Cdim];
__device__ __half g_ATT16[Mrows * Cdim];
__device__ __half g_FF16 [Mrows * FFdim];
__device__ __half g_Wq16[Cdim * 3 * Cdim];
__device__ __half g_Wa16[Cdim * Cdim];
__device__ __half g_Wf16[Cdim * FFdim];
__device__ __half g_Wm16[FFdim * Cdim];

// --------------------- fused fp32 -> fp16 weight convert -------------------
__global__ void __launch_bounds__(256)
cvt_all_kernel(const float* __restrict__ wq, const float* __restrict__ wa,
               const float* __restrict__ wf, const float* __restrict__ wm,
               __half* __restrict__ oq, __half* __restrict__ oa,
               __half* __restrict__ of, __half* __restrict__ om)
{
    const int n1 = 3 * Cdim * Cdim / 4;
    const int n2 = Cdim * Cdim / 4;
    const int n3 = Cdim * FFdim / 4;
    int i = blockIdx.x * 256 + threadIdx.x;
    const float* src; __half* dst; int j = i;
    if (j < n1)            { src = wq; dst = oq; }
    else { j -= n1;
    if (j < n2)            { src = wa; dst = oa; }
    else { j -= n2;
    if (j < n3)            { src = wf; dst = of; }
    else { j -= n3;          src = wm; dst = om; } } }
    float4 v = reinterpret_cast<const float4*>(src)[j];
    __half2 h0 = __floats2half2_rn(v.x, v.y);
    __half2 h1 = __floats2half2_rn(v.z, v.w);
    uint2 o = { *(uint32_t*)&h0, *(uint32_t*)&h1 };
    reinterpret_cast<uint2*>(dst)[j] = o;
}

// ------------------------ LayerNorm (warp per row) -------------------------
__global__ void __launch_bounds__(256)
ln_kernel(const float* __restrict__ X, const float* __restrict__ g,
          const float* __restrict__ b, __half* __restrict__ Y)
{
    int w    = threadIdx.x >> 5;
    int lane = threadIdx.x & 31;
    int row  = blockIdx.x * 8 + w;

    const float4* xr = reinterpret_cast<const float4*>(X + (size_t)row * Cdim);
    float4 v[8];
    float sum = 0.0f, sq = 0.0f;
#pragma unroll
    for (int i = 0; i < 8; i++) {
        v[i] = xr[lane + 32 * i];
        sum += v[i].x + v[i].y + v[i].z + v[i].w;
        sq  += v[i].x*v[i].x + v[i].y*v[i].y + v[i].z*v[i].z + v[i].w*v[i].w;
    }
#pragma unroll
    for (int st = 16; st > 0; st >>= 1) {
        sum += __shfl_xor_sync(0xFFFFFFFFu, sum, st);
        sq  += __shfl_xor_sync(0xFFFFFFFFu, sq,  st);
    }
    float mu   = sum * (1.0f / Cdim);
    float var  = sq  * (1.0f / Cdim) - mu * mu;
    float rstd = rsqrtf(var + 1e-5f);

    const float4* gr = reinterpret_cast<const float4*>(g);
    const float4* br = reinterpret_cast<const float4*>(b);
    uint2* yr = reinterpret_cast<uint2*>(Y + (size_t)row * Cdim);
#pragma unroll
    for (int i = 0; i < 8; i++) {
        float4 gg = gr[lane + 32 * i];
        float4 bb = br[lane + 32 * i];
        __half2 h0 = __floats2half2_rn((v[i].x - mu) * rstd * gg.x + bb.x,
                                       (v[i].y - mu) * rstd * gg.y + bb.y);
        __half2 h1 = __floats2half2_rn((v[i].z - mu) * rstd * gg.z + bb.z,
                                       (v[i].w - mu) * rstd * gg.w + bb.w);
        uint2 o = { *(uint32_t*)&h0, *(uint32_t*)&h1 };
        yr[lane + 32 * i] = o;
    }
}

// ------------------------------ common helpers -----------------------------
__device__ __forceinline__ float gelu_f(float x)
{
    float x3 = x * x * x;
    float t  = tanhf(0.7978845608028654f * (x + 0.044715f * x3));
    return 0.5f * x * (1.0f + t);
}

#define CP_ASYNC16(dst, src) \
    asm volatile("cp.async.cg.shared.global [%0], [%1], 16;" :: "r"(dst), "l"(src))
#define CP_COMMIT()   asm volatile("cp.async.commit_group;" ::: "memory")
#define CP_WAIT(n)    asm volatile("cp.async.wait_group %0;" :: "n"(n) : "memory")

__device__ __forceinline__ uint32_t smem_u32(const void* p) {
    uint32_t a;
    asm("{ .reg .u64 t; cvta.to.shared.u64 t, %1; cvt.u32.u64 %0, t; }"
        : "=r"(a) : "l"(p));
    return a;
}

__device__ __forceinline__ void ldsm_x4(uint32_t& r0, uint32_t& r1,
                                        uint32_t& r2, uint32_t& r3, uint32_t addr)
{
    asm volatile("ldmatrix.sync.aligned.m8n8.x4.shared.b16 {%0,%1,%2,%3}, [%4];"
        : "=r"(r0), "=r"(r1), "=r"(r2), "=r"(r3) : "r"(addr));
}
__device__ __forceinline__ void ldsm_x4_t(uint32_t& r0, uint32_t& r1,
                                          uint32_t& r2, uint32_t& r3, uint32_t addr)
{
    asm volatile("ldmatrix.sync.aligned.m8n8.x4.trans.shared.b16 {%0,%1,%2,%3}, [%4];"
        : "=r"(r0), "=r"(r1), "=r"(r2), "=r"(r3) : "r"(addr));
}
__device__ __forceinline__ void mma_16816(float* c, const uint32_t* a,
                                          const uint32_t* b)
{
    asm volatile("mma.sync.aligned.m16n8k16.row.col.f32.f16.f16.f32 "
        "{%0,%1,%2,%3}, {%4,%5,%6,%7}, {%8,%9}, {%0,%1,%2,%3};"
        : "+f"(c[0]), "+f"(c[1]), "+f"(c[2]), "+f"(c[3])
        : "r"(a[0]), "r"(a[1]), "r"(a[2]), "r"(a[3]), "r"(b[0]), "r"(b[1]));
}

// ---------- persistent cross-tile-pipelined raw mma.sync GEMM --------------
static constexpr int BM = 128, BN = 128, BK = 64;
static constexpr int A_BYTES = BM * BK * 2;        // 16384
static constexpr int B_BYTES = BK * BN * 2;        // 16384
static constexpr int STAGE   = A_BYTES + B_BYTES;  // 32768
static constexpr int NSTG    = 3;
static constexpr int GEMM_SMEM = NSTG * STAGE;     // 98304

template<int EPI, int OUTH>
__global__ void __launch_bounds__(256, 2)
gemm_mma(const __half* __restrict__ A, const __half* __restrict__ W,
         const float* __restrict__ bias, const float* __restrict__ R,
         void* __restrict__ Cout, int M, int N, int K)
{
    extern __shared__ __align__(128) char smem[];
    uint32_t sA_u[NSTG], sB_u[NSTG];
#pragma unroll
    for (int i = 0; i < NSTG; i++) {
        sA_u[i] = smem_u32(smem + i * STAGE);
        sB_u[i] = smem_u32(smem + i * STAGE + A_BYTES);
    }

    int tid  = threadIdx.x;
    int wid  = tid >> 5;
    int lane = tid & 31;
    int wm   = wid >> 2;
    int wn   = wid & 3;

    int l15 = lane & 15;
    int hi  = lane >> 4;
    int x   = lane & 7;

    int nk     = K / BK;
    int ntx    = N / BN;
    int ntiles = (M / BM) * ntx;
    int nmine  = (ntiles - (int)blockIdx.x + (int)gridDim.x - 1) / (int)gridDim.x;
    int total  = nmine * nk;
    if (total <= 0) return;

    // issue stage of global stream index g (tile = g/nk, stage = g%nk)
    auto issue_g = [&](int gidx, int buf) {
        int ti = gidx / nk;
        int s  = gidx - ti * nk;
        int t  = (int)blockIdx.x + ti * (int)gridDim.x;
        int m0 = (t / ntx) * BM;
        int n0 = (t % ntx) * BN;
        const __half* Ab = A + (size_t)m0 * K + s * BK;
        const __half* Wb = W + (size_t)s * BK * N + n0;
#pragma unroll
        for (int i = 0; i < 4; i++) {
            int f = tid + i * 256;
            int ra = f >> 3, ca = f & 7;
            uint32_t da = sA_u[buf] + (uint32_t)((ra * 8 + (ca ^ (ra & 7))) * 16);
            CP_ASYNC16(da, Ab + (size_t)ra * K + ca * 8);
            int rb = f >> 4, cb = f & 15;
            int pb = (cb & 8) | ((cb & 7) ^ (rb & 7));
            uint32_t db = sB_u[buf] + (uint32_t)((rb * 16 + pb) * 16);
            CP_ASYNC16(db, Wb + (size_t)rb * N + cb * 8);
        }
        CP_COMMIT();
    };

    issue_g(0, 0);
    if (total > 1) issue_g(1, 1);

    float acc[4][4][4];

    for (int g = 0; g < total; ++g) {
        int s = g % nk;
        if (s == 0) {
#pragma unroll
            for (int i = 0; i < 4; i++)
#pragma unroll
                for (int j = 0; j < 4; j++)
#pragma unroll
                    for (int r = 0; r < 4; r++) acc[i][j][r] = 0.0f;
        }
        int buf = g % NSTG;
        if (g + 1 < total) { CP_WAIT(1); } else { CP_WAIT(0); }
        __syncthreads();
        if (g + 2 < total) issue_g(g + 2, (g + 2) % NSTG);

        uint32_t aT = sA_u[buf];
        uint32_t bT = sB_u[buf];
#pragma unroll
        for (int ks = 0; ks < 4; ++ks) {
            uint32_t a[4][4];
#pragma unroll
            for (int mi = 0; mi < 4; mi++) {
                int row = wm * 64 + mi * 16 + l15;
                int ch  = (ks * 2 + hi) ^ x;
                ldsm_x4(a[mi][0], a[mi][1], a[mi][2], a[mi][3],
                        aT + (uint32_t)((row * 8 + ch) * 16));
            }
            uint32_t b[4][2];
#pragma unroll
            for (int nj = 0; nj < 2; nj++) {
                int row = ks * 16 + l15;
                int cl  = wn * 4 + nj * 2 + hi;
                int ch  = (cl & 8) | ((cl & 7) ^ x);
                uint32_t r0, r1, r2, r3;
                ldsm_x4_t(r0, r1, r2, r3, bT + (uint32_t)((row * 16 + ch) * 16));
                b[nj * 2][0] = r0; b[nj * 2][1] = r1;
                b[nj * 2 + 1][0] = r2; b[nj * 2 + 1][1] = r3;
            }
#pragma unroll
            for (int mi = 0; mi < 4; mi++)
#pragma unroll
                for (int ni = 0; ni < 4; ni++)
                    mma_16816(acc[mi][ni], a[mi], b[ni]);
        }

        if (s == nk - 1) {
            // ---- register-direct epilogue for tile g/nk ----
            int t  = (int)blockIdx.x + (g / nk) * (int)gridDim.x;
            int m0 = (t / ntx) * BM;
            int n0 = (t % ntx) * BN;
            int rbase = m0 + wm * 64 + (lane >> 2);
            int cbase = n0 + wn * 32 + (lane & 3) * 2;
#pragma unroll
            for (int mi = 0; mi < 4; mi++) {
#pragma unroll
                for (int ni = 0; ni < 4; ni++) {
                    int col = cbase + ni * 8;
                    float2 bi = *reinterpret_cast<const float2*>(bias + col);
#pragma unroll
                    for (int h = 0; h < 2; h++) {
                        int row = rbase + mi * 16 + h * 8;
                        float v0 = acc[mi][ni][h * 2 + 0] + bi.x;
                        float v1 = acc[mi][ni][h * 2 + 1] + bi.y;
                        if (EPI == 1) { v0 = gelu_f(v0); v1 = gelu_f(v1); }
                        if (EPI == 2) {
                            float2 rr = *reinterpret_cast<const float2*>(
                                R + (size_t)row * N + col);
                            v0 += rr.x; v1 += rr.y;
                        }
                        if (OUTH) {
                            __half2 hv = __floats2half2_rn(v0, v1);
                            *reinterpret_cast<__half2*>(
                                (__half*)Cout + (size_t)row * N + col) = hv;
                        } else {
                            float2 fv = { v0, v1 };
                            *reinterpret_cast<float2*>(
                                (float*)Cout + (size_t)row * N + col) = fv;
                        }
                    }
                }
            }
        }
    }
}

// ---------------- raw mma.sync register-resident flash attention -----------
// 256 threads (8 warps), 128 q rows/block, KV tiles 64, double-buffered.
// exp2-domain softmax (R11 proven config).
static constexpr int FLASH_SMEM = 16384 + 4 * 8192;   // Q(128x64) + 2*(K,V)

__global__ void __launch_bounds__(256, 2)
flash_mma(const __half* __restrict__ QKV, __half* __restrict__ ATT)
{
    extern __shared__ __align__(128) char smem[];
    uint32_t Qu = smem_u32(smem);
    uint32_t Ku[2] = { Qu + 16384, Qu + 32768 };
    uint32_t Vu[2] = { Qu + 24576, Qu + 40960 };

    int tid  = threadIdx.x;
    int w    = tid >> 5;
    int lane = tid & 31;
    int qt   = gridDim.x - 1 - blockIdx.x;      // heavy tiles first
    int bh   = blockIdx.y;
    int b    = bh >> 4;
    int h    = bh & 15;
    int q0   = qt * 128;

    auto ld_tile = [&](uint32_t dstu, const __half* src) {
#pragma unroll
        for (int i = 0; i < 2; i++) {
            int f = tid + i * 256;
            int r = f >> 3, c = f & 7;
            uint32_t d = dstu + (uint32_t)((r * 8 + (c ^ (r & 7))) * 16);
            CP_ASYNC16(d, src + (size_t)r * (3 * Cdim) + c * 8);
        }
    };

    const __half* Qg  = QKV + (size_t)(b * Tlen + q0) * (3 * Cdim) + h * HDim;
    const __half* Kg0 = QKV + (size_t)(b * Tlen) * (3 * Cdim) + Cdim + h * HDim;
#pragma unroll
    for (int i = 0; i < 4; i++) {
        int f = tid + i * 256;
        int r = f >> 3, c = f & 7;
        uint32_t d = Qu + (uint32_t)((r * 8 + (c ^ (r & 7))) * 16);
        CP_ASYNC16(d, Qg + (size_t)r * (3 * Cdim) + c * 8);
    }
    CP_COMMIT();
    ld_tile(Ku[0], Kg0);
    ld_tile(Vu[0], Kg0 + Cdim);
    CP_COMMIT();

    uint32_t qa[4][4];
    {
        CP_WAIT(1);
        __syncthreads();
        int l15_ = lane & 15, hi_ = lane >> 4;
        int row = w * 16 + l15_;
#pragma unroll
        for (int dk = 0; dk < 4; dk++) {
            int ch = (dk * 2 + hi_) ^ (row & 7);
            ldsm_x4(qa[dk][0], qa[dk][1], qa[dk][2], qa[dk][3],
                    Qu + (uint32_t)((row * 8 + ch) * 16));
        }
        const float QSC = 0.18033688f;   // log2(e) * 0.125
        __half2 sc = __floats2half2_rn(QSC, QSC);
#pragma unroll
        for (int dk = 0; dk < 4; dk++)
#pragma unroll
            for (int r = 0; r < 4; r++) {
                __half2 v = *reinterpret_cast<__half2*>(&qa[dk][r]);
                v = __hmul2(v, sc);
                qa[dk][r] = *reinterpret_cast<uint32_t*>(&v);
            }
    }

    float o[8][4];
#pragma unroll
    for (int n = 0; n < 8; n++)
#pragma unroll
        for (int r = 0; r < 4; r++) o[n][r] = 0.0f;
    float m0 = -1e30f, m1 = -1e30f, l0 = 0.0f, l1 = 0.0f;

    int g    = lane >> 3;
    int r8   = lane & 7;
    int l15  = lane & 15;
    int hi   = lane >> 4;
    int qr   = q0 + w * 16 + (lane >> 2);
    int ntm1 = q0 >> 6;
    int nt   = ntm1 + 1;

    for (int t = 0; t <= nt; ++t) {
        int buf = t & 1;
        if (t < nt) {
            const __half* Kg = QKV + (size_t)(b * Tlen + (t + 1) * 64) * (3 * Cdim)
                             + Cdim + h * HDim;
            ld_tile(Ku[buf ^ 1], Kg);
            ld_tile(Vu[buf ^ 1], Kg + Cdim);
            CP_COMMIT();
            CP_WAIT(1);
        } else {
            CP_WAIT(0);
        }
        __syncthreads();

        float s[8][4];
#pragma unroll
        for (int n = 0; n < 8; n++)
#pragma unroll
            for (int r = 0; r < 4; r++) s[n][r] = 0.0f;
#pragma unroll
        for (int dk = 0; dk < 4; dk++) {
            uint32_t kb[8][2];
#pragma unroll
            for (int p = 0; p < 4; p++) {
                int row = p * 16 + (g >> 1) * 8 + r8;
                int ch  = (dk * 2 + (g & 1)) ^ (row & 7);
                uint32_t r0, r1, r2, r3;
                ldsm_x4(r0, r1, r2, r3, Ku[buf] + (uint32_t)((row * 8 + ch) * 16));
                kb[2*p][0] = r0; kb[2*p][1] = r1;
                kb[2*p+1][0] = r2; kb[2*p+1][1] = r3;
            }
#pragma unroll
            for (int n = 0; n < 8; n++) mma_16816(s[n], qa[dk], kb[n]);
        }

        bool needmask = (t >= ntm1);
        float mx0 = -1e30f, mx1 = -1e30f;
#pragma unroll
        for (int n = 0; n < 8; n++) {
            if (needmask) {
                int col = t * 64 + n * 8 + (lane & 3) * 2;
                if (col     > qr)     s[n][0] = -1e30f;
                if (col + 1 > qr)     s[n][1] = -1e30f;
                if (col     > qr + 8) s[n][2] = -1e30f;
                if (col + 1 > qr + 8) s[n][3] = -1e30f;
            }
            mx0 = fmaxf(mx0, fmaxf(s[n][0], s[n][1]));
            mx1 = fmaxf(mx1, fmaxf(s[n][2], s[n][3]));
        }
        mx0 = fmaxf(mx0, __shfl_xor_sync(0xFFFFFFFFu, mx0, 1));
        mx0 = fmaxf(mx0, __shfl_xor_sync(0xFFFFFFFFu, mx0, 2));
        mx1 = fmaxf(mx1, __shfl_xor_sync(0xFFFFFFFFu, mx1, 1));
        mx1 = fmaxf(mx1, __shfl_xor_sync(0xFFFFFFFFu, mx1, 2));

        float mn0 = fmaxf(m0, mx0), mn1 = fmaxf(m1, mx1);
        float sc0 = exp2f(m0 - mn0), sc1 = exp2f(m1 - mn1);
        float sum0 = 0.0f, sum1 = 0.0f;
        uint32_t pa[4][4];
#pragma unroll
        for (int dk = 0; dk < 4; dk++) {
            float e00 = exp2f(s[2*dk][0]   - mn0);
            float e01 = exp2f(s[2*dk][1]   - mn0);
            float e02 = exp2f(s[2*dk][2]   - mn1);
            float e03 = exp2f(s[2*dk][3]   - mn1);
            float e10 = exp2f(s[2*dk+1][0] - mn0);
            float e11 = exp2f(s[2*dk+1][1] - mn0);
            float e12 = exp2f(s[2*dk+1][2] - mn1);
            float e13 = exp2f(s[2*dk+1][3] - mn1);
            sum0 += e00 + e01 + e10 + e11;
            sum1 += e02 + e03 + e12 + e13;
            __half2 h0 = __floats2half2_rn(e00, e01);
            __half2 h1 = __floats2half2_rn(e02, e03);
            __half2 h2 = __floats2half2_rn(e10, e11);
            __half2 h3 = __floats2half2_rn(e12, e13);
            pa[dk][0] = *reinterpret_cast<uint32_t*>(&h0);
            pa[dk][1] = *reinterpret_cast<uint32_t*>(&h1);
            pa[dk][2] = *reinterpret_cast<uint32_t*>(&h2);
            pa[dk][3] = *reinterpret_cast<uint32_t*>(&h3);
        }
        sum0 += __shfl_xor_sync(0xFFFFFFFFu, sum0, 1);
        sum0 += __shfl_xor_sync(0xFFFFFFFFu, sum0, 2);
        sum1 += __shfl_xor_sync(0xFFFFFFFFu, sum1, 1);
        sum1 += __shfl_xor_sync(0xFFFFFFFFu, sum1, 2);
        l0 = l0 * sc0 + sum0;
        l1 = l1 * sc1 + sum1;
        m0 = mn0; m1 = mn1;
#pragma unroll
        for (int n = 0; n < 8; n++) {
            o[n][0] *= sc0; o[n][1] *= sc0;
            o[n][2] *= sc1; o[n][3] *= sc1;
        }

#pragma unroll
        for (int dk = 0; dk < 4; dk++) {
            uint32_t vb[8][2];
            int row = dk * 16 + l15;
#pragma unroll
            for (int p = 0; p < 4; p++) {
                int ch = (p * 2 + hi) ^ (row & 7);
                uint32_t r0, r1, r2, r3;
                ldsm_x4_t(r0, r1, r2, r3, Vu[buf] + (uint32_t)((row * 8 + ch) * 16));
                vb[2*p][0] = r0; vb[2*p][1] = r1;
                vb[2*p+1][0] = r2; vb[2*p+1][1] = r3;
            }
#pragma unroll
            for (int n = 0; n < 8; n++) mma_16816(o[n], pa[dk], vb[n]);
        }
        __syncthreads();
    }

    float inv0 = 1.0f / l0, inv1 = 1.0f / l1;
    int row0 = q0 + w * 16 + (lane >> 2);
    __half* base = ATT + (size_t)(b * Tlen) * Cdim + h * HDim;
#pragma unroll
    for (int n = 0; n < 8; n++) {
        int col = n * 8 + (lane & 3) * 2;
        __half2 h0 = __floats2half2_rn(o[n][0] * inv0, o[n][1] * inv0);
        __half2 h1 = __floats2half2_rn(o[n][2] * inv1, o[n][3] * inv1);
        *reinterpret_cast<__half2*>(base + (size_t)row0 * Cdim + col) = h0;
        *reinterpret_cast<__half2*>(base + (size_t)(row0 + 8) * Cdim + col) = h1;
    }
}

// -------------------------------- launcher ---------------------------------
extern "C" void kernel_launch(void* const* d_in, const int* in_sizes, int n_in,
                              void* d_out, int out_size)
{
    const float* x           = (const float*)d_in[0];
    const float* ln1_g       = (const float*)d_in[1];
    const float* ln1_b       = (const float*)d_in[2];
    const float* w_qkv       = (const float*)d_in[3];
    const float* b_qkv       = (const float*)d_in[4];
    const float* w_attn_proj = (const float*)d_in[5];
    const float* b_attn_proj = (const float*)d_in[6];
    const float* ln2_g       = (const float*)d_in[7];
    const float* ln2_b       = (const float*)d_in[8];
    const float* w_fc        = (const float*)d_in[9];
    const float* b_fc        = (const float*)d_in[10];
    const float* w_mlp_proj  = (const float*)d_in[11];
    const float* b_mlp_proj  = (const float*)d_in[12];
    float* out = (float*)d_out;

    float *X1;
    __half *H16, *QKV16, *ATT16, *FF16, *Wq16, *Wa16, *Wf16, *Wm16;
    cudaGetSymbolAddress((void**)&X1,    g_X1);
    cudaGetSymbolAddress((void**)&H16,   g_H16);
    cudaGetSymbolAddress((void**)&QKV16, g_QKV16);
    cudaGetSymbolAddress((void**)&ATT16, g_ATT16);
    cudaGetSymbolAddress((void**)&FF16,  g_FF16);
    cudaGetSymbolAddress((void**)&Wq16,  g_Wq16);
    cudaGetSymbolAddress((void**)&Wa16,  g_Wa16);
    cudaGetSymbolAddress((void**)&Wf16,  g_Wf16);
    cudaGetSymbolAddress((void**)&Wm16,  g_Wm16);

    cudaFuncSetAttribute(gemm_mma<0,1>, cudaFuncAttributeMaxDynamicSharedMemorySize, GEMM_SMEM);
    cudaFuncSetAttribute(gemm_mma<1,1>, cudaFuncAttributeMaxDynamicSharedMemorySize, GEMM_SMEM);
    cudaFuncSetAttribute(gemm_mma<2,0>, cudaFuncAttributeMaxDynamicSharedMemorySize, GEMM_SMEM);
    cudaFuncSetAttribute(flash_mma, cudaFuncAttributeMaxDynamicSharedMemorySize, FLASH_SMEM);

    // weight conversion (single launch)
    {
        int total4 = (3 * Cdim * Cdim + Cdim * Cdim + Cdim * FFdim + FFdim * Cdim) / 4;
        cvt_all_kernel<<<(total4 + 255) / 256, 256>>>(
            w_qkv, w_attn_proj, w_fc, w_mlp_proj, Wq16, Wa16, Wf16, Wm16);
    }

    // 1. h = LN1(x)                      (fp16 out)
    ln_kernel<<<Mrows / 8, 256>>>(x, ln1_g, ln1_b, H16);
    // 2. qkv = h @ w_qkv + b             (fp16 out)
    gemm_mma<0,1><<<PERSIST_CTAS, 256, GEMM_SMEM>>>(
        H16, Wq16, b_qkv, nullptr, QKV16, Mrows, 3 * Cdim, Cdim);
    // 3. causal flash attention (raw mma) (fp16 out)
    flash_mma<<<dim3(Tlen / 128, Bsz * NHead), 256, FLASH_SMEM>>>(QKV16, ATT16);
    // 4. x1 = x + attn @ w_attn_proj + b (fp32 out)
    gemm_mma<2,0><<<PERSIST_CTAS, 256, GEMM_SMEM>>>(
        ATT16, Wa16, b_attn_proj, x, X1, Mrows, Cdim, Cdim);
    // 5. h = LN2(x1)                     (fp16 out)
    ln_kernel<<<Mrows / 8, 256>>>(X1, ln2_g, ln2_b, H16);
    // 6. ff = gelu(h @ w_fc + b)         (fp16 out)
    gemm_mma<1,1><<<PERSIST_CTAS, 256, GEMM_SMEM>>>(
        H16, Wf16, b_fc, nullptr, FF16, Mrows, FFdim, Cdim);
    // 7. out = x1 + ff @ w_mlp_proj + b  (fp32 out)
    gemm_mma<2,0><<<PERSIST_CTAS, 256, GEMM_SMEM>>>(
        FF16, Wm16, b_mlp_proj, X1, out, Mrows, Cdim, FFdim);
}

// round 16
// speedup vs baseline: 1.1628x; 1.1628x over previous
#include <cuda_runtime.h>
#include <cuda_fp16.h>
#include <math.h>
#include <stdint.h>

// ---------------------------------------------------------------------------
// TransformerBlock B=4,T=2048,C=1024,NH=16,HD=64,FF=4096 fp32.
// R15: R11 config (grid-launched 128x128x64 3-stage GEMM, 2 CTA/SM; exp2
//      flash) + MUFU tanh.approx for the GELU epilogue.
// ---------------------------------------------------------------------------

#define Bsz   4
#define Tlen  2048
#define Cdim  1024
#define NHead 16
#define HDim  64
#define FFdim 4096
#define Mrows (Bsz * Tlen)   // 8192

// ------------------------- scratch (device globals) ------------------------
__device__ float  g_X1 [Mrows * Cdim];
__device__ __half g_H16  [Mrows * Cdim];
__device__ __half g_QKV16[Mrows * 3 * Cdim];
__device__ __half g_ATT16[Mrows * Cdim];
__device__ __half g_FF16 [Mrows * FFdim];
__device__ __half g_Wq16[Cdim * 3 * Cdim];
__device__ __half g_Wa16[Cdim * Cdim];
__device__ __half g_Wf16[Cdim * FFdim];
__device__ __half g_Wm16[FFdim * Cdim];

// --------------------- fused fp32 -> fp16 weight convert -------------------
__global__ void __launch_bounds__(256)
cvt_all_kernel(const float* __restrict__ wq, const float* __restrict__ wa,
               const float* __restrict__ wf, const float* __restrict__ wm,
               __half* __restrict__ oq, __half* __restrict__ oa,
               __half* __restrict__ of, __half* __restrict__ om)
{
    const int n1 = 3 * Cdim * Cdim / 4;
    const int n2 = Cdim * Cdim / 4;
    const int n3 = Cdim * FFdim / 4;
    int i = blockIdx.x * 256 + threadIdx.x;
    const float* src; __half* dst; int j = i;
    if (j < n1)            { src = wq; dst = oq; }
    else { j -= n1;
    if (j < n2)            { src = wa; dst = oa; }
    else { j -= n2;
    if (j < n3)            { src = wf; dst = of; }
    else { j -= n3;          src = wm; dst = om; } } }
    float4 v = reinterpret_cast<const float4*>(src)[j];
    __half2 h0 = __floats2half2_rn(v.x, v.y);
    __half2 h1 = __floats2half2_rn(v.z, v.w);
    uint2 o = { *(uint32_t*)&h0, *(uint32_t*)&h1 };
    reinterpret_cast<uint2*>(dst)[j] = o;
}

// ------------------------ LayerNorm (warp per row) -------------------------
__global__ void __launch_bounds__(256)
ln_kernel(const float* __restrict__ X, const float* __restrict__ g,
          const float* __restrict__ b, __half* __restrict__ Y)
{
    int w    = threadIdx.x >> 5;
    int lane = threadIdx.x & 31;
    int row  = blockIdx.x * 8 + w;

    const float4* xr = reinterpret_cast<const float4*>(X + (size_t)row * Cdim);
    float4 v[8];
    float sum = 0.0f, sq = 0.0f;
#pragma unroll
    for (int i = 0; i < 8; i++) {
        v[i] = xr[lane + 32 * i];
        sum += v[i].x + v[i].y + v[i].z + v[i].w;
        sq  += v[i].x*v[i].x + v[i].y*v[i].y + v[i].z*v[i].z + v[i].w*v[i].w;
    }
#pragma unroll
    for (int st = 16; st > 0; st >>= 1) {
        sum += __shfl_xor_sync(0xFFFFFFFFu, sum, st);
        sq  += __shfl_xor_sync(0xFFFFFFFFu, sq,  st);
    }
    float mu   = sum * (1.0f / Cdim);
    float var  = sq  * (1.0f / Cdim) - mu * mu;
    float rstd = rsqrtf(var + 1e-5f);

    const float4* gr = reinterpret_cast<const float4*>(g);
    const float4* br = reinterpret_cast<const float4*>(b);
    uint2* yr = reinterpret_cast<uint2*>(Y + (size_t)row * Cdim);
#pragma unroll
    for (int i = 0; i < 8; i++) {
        float4 gg = gr[lane + 32 * i];
        float4 bb = br[lane + 32 * i];
        __half2 h0 = __floats2half2_rn((v[i].x - mu) * rstd * gg.x + bb.x,
                                       (v[i].y - mu) * rstd * gg.y + bb.y);
        __half2 h1 = __floats2half2_rn((v[i].z - mu) * rstd * gg.z + bb.z,
                                       (v[i].w - mu) * rstd * gg.w + bb.w);
        uint2 o = { *(uint32_t*)&h0, *(uint32_t*)&h1 };
        yr[lane + 32 * i] = o;
    }
}

// ------------------------------ common helpers -----------------------------
__device__ __forceinline__ float gelu_f(float x)
{
    float x3 = x * x * x;
    float u  = 0.7978845608028654f * (x + 0.044715f * x3);
    float t;
    asm("tanh.approx.f32 %0, %1;" : "=f"(t) : "f"(u));
    return 0.5f * x * (1.0f + t);
}

#define CP_ASYNC16(dst, src) \
    asm volatile("cp.async.cg.shared.global [%0], [%1], 16;" :: "r"(dst), "l"(src))
#define CP_COMMIT()   asm volatile("cp.async.commit_group;" ::: "memory")
#define CP_WAIT(n)    asm volatile("cp.async.wait_group %0;" :: "n"(n) : "memory")

__device__ __forceinline__ uint32_t smem_u32(const void* p) {
    uint32_t a;
    asm("{ .reg .u64 t; cvta.to.shared.u64 t, %1; cvt.u32.u64 %0, t; }"
        : "=r"(a) : "l"(p));
    return a;
}

__device__ __forceinline__ void ldsm_x4(uint32_t& r0, uint32_t& r1,
                                        uint32_t& r2, uint32_t& r3, uint32_t addr)
{
    asm volatile("ldmatrix.sync.aligned.m8n8.x4.shared.b16 {%0,%1,%2,%3}, [%4];"
        : "=r"(r0), "=r"(r1), "=r"(r2), "=r"(r3) : "r"(addr));
}
__device__ __forceinline__ void ldsm_x4_t(uint32_t& r0, uint32_t& r1,
                                          uint32_t& r2, uint32_t& r3, uint32_t addr)
{
    asm volatile("ldmatrix.sync.aligned.m8n8.x4.trans.shared.b16 {%0,%1,%2,%3}, [%4];"
        : "=r"(r0), "=r"(r1), "=r"(r2), "=r"(r3) : "r"(addr));
}
__device__ __forceinline__ void mma_16816(float* c, const uint32_t* a,
                                          const uint32_t* b)
{
    asm volatile("mma.sync.aligned.m16n8k16.row.col.f32.f16.f16.f32 "
        "{%0,%1,%2,%3}, {%4,%5,%6,%7}, {%8,%9}, {%0,%1,%2,%3};"
        : "+f"(c[0]), "+f"(c[1]), "+f"(c[2]), "+f"(c[3])
        : "r"(a[0]), "r"(a[1]), "r"(a[2]), "r"(a[3]), "r"(b[0]), "r"(b[1]));
}

// --------------------- raw mma.sync GEMM (3-stage ring) --------------------
static constexpr int BM = 128, BN = 128, BK = 64;
static constexpr int A_BYTES = BM * BK * 2;        // 16384
static constexpr int B_BYTES = BK * BN * 2;        // 16384
static constexpr int STAGE   = A_BYTES + B_BYTES;  // 32768
static constexpr int NSTG    = 3;
static constexpr int GEMM_SMEM = NSTG * STAGE;     // 98304

template<int EPI, int OUTH>
__global__ void __launch_bounds__(256, 2)
gemm_mma(const __half* __restrict__ A, const __half* __restrict__ W,
         const float* __restrict__ bias, const float* __restrict__ R,
         void* __restrict__ Cout, int M, int N, int K)
{
    extern __shared__ __align__(128) char smem[];
    uint32_t sA_u[NSTG], sB_u[NSTG];
#pragma unroll
    for (int i = 0; i < NSTG; i++) {
        sA_u[i] = smem_u32(smem + i * STAGE);
        sB_u[i] = smem_u32(smem + i * STAGE + A_BYTES);
    }

    int tid  = threadIdx.x;
    int wid  = tid >> 5;
    int lane = tid & 31;
    int wm   = wid >> 2;
    int wn   = wid & 3;
    int m0   = blockIdx.y * BM;
    int n0   = blockIdx.x * BN;

    float acc[4][4][4];
#pragma unroll
    for (int i = 0; i < 4; i++)
#pragma unroll
        for (int j = 0; j < 4; j++)
#pragma unroll
            for (int r = 0; r < 4; r++) acc[i][j][r] = 0.0f;

    int nk = K / BK;

    auto issue_stage = [&](int s, int buf) {
        const __half* Ab = A + (size_t)m0 * K + s * BK;
        const __half* Wb = W + (size_t)s * BK * N + n0;
#pragma unroll
        for (int i = 0; i < 4; i++) {
            int f = tid + i * 256;
            int ra = f >> 3, ca = f & 7;
            uint32_t da = sA_u[buf] + (uint32_t)((ra * 8 + (ca ^ (ra & 7))) * 16);
            CP_ASYNC16(da, Ab + (size_t)ra * K + ca * 8);
            int rb = f >> 4, cb = f & 15;
            int pb = (cb & 8) | ((cb & 7) ^ (rb & 7));
            uint32_t db = sB_u[buf] + (uint32_t)((rb * 16 + pb) * 16);
            CP_ASYNC16(db, Wb + (size_t)rb * N + cb * 8);
        }
        CP_COMMIT();
    };

    issue_stage(0, 0);
    issue_stage(1, 1);

    int l15 = lane & 15;
    int hi  = lane >> 4;
    int x   = lane & 7;

    for (int s = 0; s < nk; ++s) {
        int buf = s % NSTG;
        if (s + 1 < nk) { CP_WAIT(1); } else { CP_WAIT(0); }
        __syncthreads();
        if (s + 2 < nk) issue_stage(s + 2, (s + 2) % NSTG);

        uint32_t aT = sA_u[buf];
        uint32_t bT = sB_u[buf];
#pragma unroll
        for (int ks = 0; ks < 4; ++ks) {
            uint32_t a[4][4];
#pragma unroll
            for (int mi = 0; mi < 4; mi++) {
                int row = wm * 64 + mi * 16 + l15;
                int ch  = (ks * 2 + hi) ^ x;
                ldsm_x4(a[mi][0], a[mi][1], a[mi][2], a[mi][3],
                        aT + (uint32_t)((row * 8 + ch) * 16));
            }
            uint32_t b[4][2];
#pragma unroll
            for (int nj = 0; nj < 2; nj++) {
                int row = ks * 16 + l15;
                int cl  = wn * 4 + nj * 2 + hi;
                int ch  = (cl & 8) | ((cl & 7) ^ x);
                uint32_t r0, r1, r2, r3;
                ldsm_x4_t(r0, r1, r2, r3, bT + (uint32_t)((row * 16 + ch) * 16));
                b[nj * 2][0] = r0; b[nj * 2][1] = r1;
                b[nj * 2 + 1][0] = r2; b[nj * 2 + 1][1] = r3;
            }
#pragma unroll
            for (int mi = 0; mi < 4; mi++)
#pragma unroll
                for (int ni = 0; ni < 4; ni++)
                    mma_16816(acc[mi][ni], a[mi], b[ni]);
        }
    }

    int rbase = m0 + wm * 64 + (lane >> 2);
    int cbase = n0 + wn * 32 + (lane & 3) * 2;
#pragma unroll
    for (int mi = 0; mi < 4; mi++) {
#pragma unroll
        for (int ni = 0; ni < 4; ni++) {
            int col = cbase + ni * 8;
            float2 bi = *reinterpret_cast<const float2*>(bias + col);
#pragma unroll
            for (int h = 0; h < 2; h++) {
                int row = rbase + mi * 16 + h * 8;
                float v0 = acc[mi][ni][h * 2 + 0] + bi.x;
                float v1 = acc[mi][ni][h * 2 + 1] + bi.y;
                if (EPI == 1) { v0 = gelu_f(v0); v1 = gelu_f(v1); }
                if (EPI == 2) {
                    float2 rr = *reinterpret_cast<const float2*>(
                        R + (size_t)row * N + col);
                    v0 += rr.x; v1 += rr.y;
                }
                if (OUTH) {
                    __half2 hv = __floats2half2_rn(v0, v1);
                    *reinterpret_cast<__half2*>(
                        (__half*)Cout + (size_t)row * N + col) = hv;
                } else {
                    float2 fv = { v0, v1 };
                    *reinterpret_cast<float2*>(
                        (float*)Cout + (size_t)row * N + col) = fv;
                }
            }
        }
    }
}

// ---------------- raw mma.sync register-resident flash attention -----------
// 256 threads (8 warps), 128 q rows/block, KV tiles 64, double-buffered.
// exp2-domain softmax.
static constexpr int FLASH_SMEM = 16384 + 4 * 8192;   // Q(128x64) + 2*(K,V)

__global__ void __launch_bounds__(256, 2)
flash_mma(const __half* __restrict__ QKV, __half* __restrict__ ATT)
{
    extern __shared__ __align__(128) char smem[];
    uint32_t Qu = smem_u32(smem);
    uint32_t Ku[2] = { Qu + 16384, Qu + 32768 };
    uint32_t Vu[2] = { Qu + 24576, Qu + 40960 };

    int tid  = threadIdx.x;
    int w    = tid >> 5;
    int lane = tid & 31;
    int qt   = gridDim.x - 1 - blockIdx.x;      // heavy tiles first
    int bh   = blockIdx.y;
    int b    = bh >> 4;
    int h    = bh & 15;
    int q0   = qt * 128;

    auto ld_tile = [&](uint32_t dstu, const __half* src) {
#pragma unroll
        for (int i = 0; i < 2; i++) {
            int f = tid + i * 256;
            int r = f >> 3, c = f & 7;
            uint32_t d = dstu + (uint32_t)((r * 8 + (c ^ (r & 7))) * 16);
            CP_ASYNC16(d, src + (size_t)r * (3 * Cdim) + c * 8);
        }
    };

    const __half* Qg  = QKV + (size_t)(b * Tlen + q0) * (3 * Cdim) + h * HDim;
    const __half* Kg0 = QKV + (size_t)(b * Tlen) * (3 * Cdim) + Cdim + h * HDim;
#pragma unroll
    for (int i = 0; i < 4; i++) {
        int f = tid + i * 256;
        int r = f >> 3, c = f & 7;
        uint32_t d = Qu + (uint32_t)((r * 8 + (c ^ (r & 7))) * 16);
        CP_ASYNC16(d, Qg + (size_t)r * (3 * Cdim) + c * 8);
    }
    CP_COMMIT();
    ld_tile(Ku[0], Kg0);
    ld_tile(Vu[0], Kg0 + Cdim);
    CP_COMMIT();

    uint32_t qa[4][4];
    {
        CP_WAIT(1);
        __syncthreads();
        int l15_ = lane & 15, hi_ = lane >> 4;
        int row = w * 16 + l15_;
#pragma unroll
        for (int dk = 0; dk < 4; dk++) {
            int ch = (dk * 2 + hi_) ^ (row & 7);
            ldsm_x4(qa[dk][0], qa[dk][1], qa[dk][2], qa[dk][3],
                    Qu + (uint32_t)((row * 8 + ch) * 16));
        }
        const float QSC = 0.18033688f;   // log2(e) * 0.125
        __half2 sc = __floats2half2_rn(QSC, QSC);
#pragma unroll
        for (int dk = 0; dk < 4; dk++)
#pragma unroll
            for (int r = 0; r < 4; r++) {
                __half2 v = *reinterpret_cast<__half2*>(&qa[dk][r]);
                v = __hmul2(v, sc);
                qa[dk][r] = *reinterpret_cast<uint32_t*>(&v);
            }
    }

    float o[8][4];
#pragma unroll
    for (int n = 0; n < 8; n++)
#pragma unroll
        for (int r = 0; r < 4; r++) o[n][r] = 0.0f;
    float m0 = -1e30f, m1 = -1e30f, l0 = 0.0f, l1 = 0.0f;

    int g    = lane >> 3;
    int r8   = lane & 7;
    int l15  = lane & 15;
    int hi   = lane >> 4;
    int qr   = q0 + w * 16 + (lane >> 2);
    int ntm1 = q0 >> 6;
    int nt   = ntm1 + 1;

    for (int t = 0; t <= nt; ++t) {
        int buf = t & 1;
        if (t < nt) {
            const __half* Kg = QKV + (size_t)(b * Tlen + (t + 1) * 64) * (3 * Cdim)
                             + Cdim + h * HDim;
            ld_tile(Ku[buf ^ 1], Kg);
            ld_tile(Vu[buf ^ 1], Kg + Cdim);
            CP_COMMIT();
            CP_WAIT(1);
        } else {
            CP_WAIT(0);
        }
        __syncthreads();

        float s[8][4];
#pragma unroll
        for (int n = 0; n < 8; n++)
#pragma unroll
            for (int r = 0; r < 4; r++) s[n][r] = 0.0f;
#pragma unroll
        for (int dk = 0; dk < 4; dk++) {
            uint32_t kb[8][2];
#pragma unroll
            for (int p = 0; p < 4; p++) {
                int row = p * 16 + (g >> 1) * 8 + r8;
                int ch  = (dk * 2 + (g & 1)) ^ (row & 7);
                uint32_t r0, r1, r2, r3;
                ldsm_x4(r0, r1, r2, r3, Ku[buf] + (uint32_t)((row * 8 + ch) * 16));
                kb[2*p][0] = r0; kb[2*p][1] = r1;
                kb[2*p+1][0] = r2; kb[2*p+1][1] = r3;
            }
#pragma unroll
            for (int n = 0; n < 8; n++) mma_16816(s[n], qa[dk], kb[n]);
        }

        bool needmask = (t >= ntm1);
        float mx0 = -1e30f, mx1 = -1e30f;
#pragma unroll
        for (int n = 0; n < 8; n++) {
            if (needmask) {
                int col = t * 64 + n * 8 + (lane & 3) * 2;
                if (col     > qr)     s[n][0] = -1e30f;
                if (col + 1 > qr)     s[n][1] = -1e30f;
                if (col     > qr + 8) s[n][2] = -1e30f;
                if (col + 1 > qr + 8) s[n][3] = -1e30f;
            }
            mx0 = fmaxf(mx0, fmaxf(s[n][0], s[n][1]));
            mx1 = fmaxf(mx1, fmaxf(s[n][2], s[n][3]));
        }
        mx0 = fmaxf(mx0, __shfl_xor_sync(0xFFFFFFFFu, mx0, 1));
        mx0 = fmaxf(mx0, __shfl_xor_sync(0xFFFFFFFFu, mx0, 2));
        mx1 = fmaxf(mx1, __shfl_xor_sync(0xFFFFFFFFu, mx1, 1));
        mx1 = fmaxf(mx1, __shfl_xor_sync(0xFFFFFFFFu, mx1, 2));

        float mn0 = fmaxf(m0, mx0), mn1 = fmaxf(m1, mx1);
        float sc0 = exp2f(m0 - mn0), sc1 = exp2f(m1 - mn1);
        float sum0 = 0.0f, sum1 = 0.0f;
        uint32_t pa[4][4];
#pragma unroll
        for (int dk = 0; dk < 4; dk++) {
            float e00 = exp2f(s[2*dk][0]   - mn0);
            float e01 = exp2f(s[2*dk][1]   - mn0);
            float e02 = exp2f(s[2*dk][2]   - mn1);
            float e03 = exp2f(s[2*dk][3]   - mn1);
            float e10 = exp2f(s[2*dk+1][0] - mn0);
            float e11 = exp2f(s[2*dk+1][1] - mn0);
            float e12 = exp2f(s[2*dk+1][2] - mn1);
            float e13 = exp2f(s[2*dk+1][3] - mn1);
            sum0 += e00 + e01 + e10 + e11;
            sum1 += e02 + e03 + e12 + e13;
            __half2 h0 = __floats2half2_rn(e00, e01);
            __half2 h1 = __floats2half2_rn(e02, e03);
            __half2 h2 = __floats2half2_rn(e10, e11);
            __half2 h3 = __floats2half2_rn(e12, e13);
            pa[dk][0] = *reinterpret_cast<uint32_t*>(&h0);
            pa[dk][1] = *reinterpret_cast<uint32_t*>(&h1);
            pa[dk][2] = *reinterpret_cast<uint32_t*>(&h2);
            pa[dk][3] = *reinterpret_cast<uint32_t*>(&h3);
        }
        sum0 += __shfl_xor_sync(0xFFFFFFFFu, sum0, 1);
        sum0 += __shfl_xor_sync(0xFFFFFFFFu, sum0, 2);
        sum1 += __shfl_xor_sync(0xFFFFFFFFu, sum1, 1);
        sum1 += __shfl_xor_sync(0xFFFFFFFFu, sum1, 2);
        l0 = l0 * sc0 + sum0;
        l1 = l1 * sc1 + sum1;
        m0 = mn0; m1 = mn1;
#pragma unroll
        for (int n = 0; n < 8; n++) {
            o[n][0] *= sc0; o[n][1] *= sc0;
            o[n][2] *= sc1; o[n][3] *= sc1;
        }

#pragma unroll
        for (int dk = 0; dk < 4; dk++) {
            uint32_t vb[8][2];
            int row = dk * 16 + l15;
#pragma unroll
            for (int p = 0; p < 4; p++) {
                int ch = (p * 2 + hi) ^ (row & 7);
                uint32_t r0, r1, r2, r3;
                ldsm_x4_t(r0, r1, r2, r3, Vu[buf] + (uint32_t)((row * 8 + ch) * 16));
                vb[2*p][0] = r0; vb[2*p][1] = r1;
                vb[2*p+1][0] = r2; vb[2*p+1][1] = r3;
            }
#pragma unroll
            for (int n = 0; n < 8; n++) mma_16816(o[n], pa[dk], vb[n]);
        }
        __syncthreads();
    }

    float inv0 = 1.0f / l0, inv1 = 1.0f / l1;
    int row0 = q0 + w * 16 + (lane >> 2);
    __half* base = ATT + (size_t)(b * Tlen) * Cdim + h * HDim;
#pragma unroll
    for (int n = 0; n < 8; n++) {
        int col = n * 8 + (lane & 3) * 2;
        __half2 h0 = __floats2half2_rn(o[n][0] * inv0, o[n][1] * inv0);
        __half2 h1 = __floats2half2_rn(o[n][2] * inv1, o[n][3] * inv1);
        *reinterpret_cast<__half2*>(base + (size_t)row0 * Cdim + col) = h0;
        *reinterpret_cast<__half2*>(base + (size_t)(row0 + 8) * Cdim + col) = h1;
    }
}

// -------------------------------- launcher ---------------------------------
extern "C" void kernel_launch(void* const* d_in, const int* in_sizes, int n_in,
                              void* d_out, int out_size)
{
    const float* x           = (const float*)d_in[0];
    const float* ln1_g       = (const float*)d_in[1];
    const float* ln1_b       = (const float*)d_in[2];
    const float* w_qkv       = (const float*)d_in[3];
    const float* b_qkv       = (const float*)d_in[4];
    const float* w_attn_proj = (const float*)d_in[5];
    const float* b_attn_proj = (const float*)d_in[6];
    const float* ln2_g       = (const float*)d_in[7];
    const float* ln2_b       = (const float*)d_in[8];
    const float* w_fc        = (const float*)d_in[9];
    const float* b_fc        = (const float*)d_in[10];
    const float* w_mlp_proj  = (const float*)d_in[11];
    const float* b_mlp_proj  = (const float*)d_in[12];
    float* out = (float*)d_out;

    float *X1;
    __half *H16, *QKV16, *ATT16, *FF16, *Wq16, *Wa16, *Wf16, *Wm16;
    cudaGetSymbolAddress((void**)&X1,    g_X1);
    cudaGetSymbolAddress((void**)&H16,   g_H16);
    cudaGetSymbolAddress((void**)&QKV16, g_QKV16);
    cudaGetSymbolAddress((void**)&ATT16, g_ATT16);
    cudaGetSymbolAddress((void**)&FF16,  g_FF16);
    cudaGetSymbolAddress((void**)&Wq16,  g_Wq16);
    cudaGetSymbolAddress((void**)&Wa16,  g_Wa16);
    cudaGetSymbolAddress((void**)&Wf16,  g_Wf16);
    cudaGetSymbolAddress((void**)&Wm16,  g_Wm16);

    cudaFuncSetAttribute(gemm_mma<0,1>, cudaFuncAttributeMaxDynamicSharedMemorySize, GEMM_SMEM);
    cudaFuncSetAttribute(gemm_mma<1,1>, cudaFuncAttributeMaxDynamicSharedMemorySize, GEMM_SMEM);
    cudaFuncSetAttribute(gemm_mma<2,0>, cudaFuncAttributeMaxDynamicSharedMemorySize, GEMM_SMEM);
    cudaFuncSetAttribute(flash_mma, cudaFuncAttributeMaxDynamicSharedMemorySize, FLASH_SMEM);

    // weight conversion (single launch)
    {
        int total4 = (3 * Cdim * Cdim + Cdim * Cdim + Cdim * FFdim + FFdim * Cdim) / 4;
        cvt_all_kernel<<<(total4 + 255) / 256, 256>>>(
            w_qkv, w_attn_proj, w_fc, w_mlp_proj, Wq16, Wa16, Wf16, Wm16);
    }

    // 1. h = LN1(x)                      (fp16 out)
    ln_kernel<<<Mrows / 8, 256>>>(x, ln1_g, ln1_b, H16);
    // 2. qkv = h @ w_qkv + b             (fp16 out)
    gemm_mma<0,1><<<dim3(3 * Cdim / BN, Mrows / BM), 256, GEMM_SMEM>>>(
        H16, Wq16, b_qkv, nullptr, QKV16, Mrows, 3 * Cdim, Cdim);
    // 3. causal flash attention (raw mma) (fp16 out)
    flash_mma<<<dim3(Tlen / 128, Bsz * NHead), 256, FLASH_SMEM>>>(QKV16, ATT16);
    // 4. x1 = x + attn @ w_attn_proj + b (fp32 out)
    gemm_mma<2,0><<<dim3(Cdim / BN, Mrows / BM), 256, GEMM_SMEM>>>(
        ATT16, Wa16, b_attn_proj, x, X1, Mrows, Cdim, Cdim);
    // 5. h = LN2(x1)                     (fp16 out)
    ln_kernel<<<Mrows / 8, 256>>>(X1, ln2_g, ln2_b, H16);
    // 6. ff = gelu(h @ w_fc + b)         (fp16 out)
    gemm_mma<1,1><<<dim3(FFdim / BN, Mrows / BM), 256, GEMM_SMEM>>>(
        H16, Wf16, b_fc, nullptr, FF16, Mrows, FFdim, Cdim);
    // 7. out = x1 + ff @ w_mlp_proj + b  (fp32 out)
    gemm_mma<2,0><<<dim3(Cdim / BN, Mrows / BM), 256, GEMM_SMEM>>>(
        FF16, Wm16, b_mlp_proj, X1, out, Mrows, Cdim, FFdim);
}

// round 17
// speedup vs baseline: 1.1951x; 1.0277x over previous
#include <cuda_runtime.h>
#include <cuda_fp16.h>
#include <math.h>
#include <stdint.h>

// ---------------------------------------------------------------------------
// TransformerBlock B=4,T=2048,C=1024,NH=16,HD=64,FF=4096 fp32.
// R16: R15 + hoisted loader addressing (precomputed swizzled dsts, running
//      src pointers) in both the GEMM stage loader and the flash KV loader.
// ---------------------------------------------------------------------------

#define Bsz   4
#define Tlen  2048
#define Cdim  1024
#define NHead 16
#define HDim  64
#define FFdim 4096
#define Mrows (Bsz * Tlen)   // 8192

// ------------------------- scratch (device globals) ------------------------
__device__ float  g_X1 [Mrows * Cdim];
__device__ __half g_H16  [Mrows * Cdim];
__device__ __half g_QKV16[Mrows * 3 * Cdim];
__device__ __half g_ATT16[Mrows * Cdim];
__device__ __half g_FF16 [Mrows * FFdim];
__device__ __half g_Wq16[Cdim * 3 * Cdim];
__device__ __half g_Wa16[Cdim * Cdim];
__device__ __half g_Wf16[Cdim * FFdim];
__device__ __half g_Wm16[FFdim * Cdim];

// --------------------- fused fp32 -> fp16 weight convert -------------------
__global__ void __launch_bounds__(256)
cvt_all_kernel(const float* __restrict__ wq, const float* __restrict__ wa,
               const float* __restrict__ wf, const float* __restrict__ wm,
               __half* __restrict__ oq, __half* __restrict__ oa,
               __half* __restrict__ of, __half* __restrict__ om)
{
    const int n1 = 3 * Cdim * Cdim / 4;
    const int n2 = Cdim * Cdim / 4;
    const int n3 = Cdim * FFdim / 4;
    int i = blockIdx.x * 256 + threadIdx.x;
    const float* src; __half* dst; int j = i;
    if (j < n1)            { src = wq; dst = oq; }
    else { j -= n1;
    if (j < n2)            { src = wa; dst = oa; }
    else { j -= n2;
    if (j < n3)            { src = wf; dst = of; }
    else { j -= n3;          src = wm; dst = om; } } }
    float4 v = reinterpret_cast<const float4*>(src)[j];
    __half2 h0 = __floats2half2_rn(v.x, v.y);
    __half2 h1 = __floats2half2_rn(v.z, v.w);
    uint2 o = { *(uint32_t*)&h0, *(uint32_t*)&h1 };
    reinterpret_cast<uint2*>(dst)[j] = o;
}

// ------------------------ LayerNorm (warp per row) -------------------------
__global__ void __launch_bounds__(256)
ln_kernel(const float* __restrict__ X, const float* __restrict__ g,
          const float* __restrict__ b, __half* __restrict__ Y)
{
    int w    = threadIdx.x >> 5;
    int lane = threadIdx.x & 31;
    int row  = blockIdx.x * 8 + w;

    const float4* xr = reinterpret_cast<const float4*>(X + (size_t)row * Cdim);
    float4 v[8];
    float sum = 0.0f, sq = 0.0f;
#pragma unroll
    for (int i = 0; i < 8; i++) {
        v[i] = xr[lane + 32 * i];
        sum += v[i].x + v[i].y + v[i].z + v[i].w;
        sq  += v[i].x*v[i].x + v[i].y*v[i].y + v[i].z*v[i].z + v[i].w*v[i].w;
    }
#pragma unroll
    for (int st = 16; st > 0; st >>= 1) {
        sum += __shfl_xor_sync(0xFFFFFFFFu, sum, st);
        sq  += __shfl_xor_sync(0xFFFFFFFFu, sq,  st);
    }
    float mu   = sum * (1.0f / Cdim);
    float var  = sq  * (1.0f / Cdim) - mu * mu;
    float rstd = rsqrtf(var + 1e-5f);

    const float4* gr = reinterpret_cast<const float4*>(g);
    const float4* br = reinterpret_cast<const float4*>(b);
    uint2* yr = reinterpret_cast<uint2*>(Y + (size_t)row * Cdim);
#pragma unroll
    for (int i = 0; i < 8; i++) {
        float4 gg = gr[lane + 32 * i];
        float4 bb = br[lane + 32 * i];
        __half2 h0 = __floats2half2_rn((v[i].x - mu) * rstd * gg.x + bb.x,
                                       (v[i].y - mu) * rstd * gg.y + bb.y);
        __half2 h1 = __floats2half2_rn((v[i].z - mu) * rstd * gg.z + bb.z,
                                       (v[i].w - mu) * rstd * gg.w + bb.w);
        uint2 o = { *(uint32_t*)&h0, *(uint32_t*)&h1 };
        yr[lane + 32 * i] = o;
    }
}

// ------------------------------ common helpers -----------------------------
__device__ __forceinline__ float gelu_f(float x)
{
    float x3 = x * x * x;
    float u  = 0.7978845608028654f * (x + 0.044715f * x3);
    float t;
    asm("tanh.approx.f32 %0, %1;" : "=f"(t) : "f"(u));
    return 0.5f * x * (1.0f + t);
}

#define CP_ASYNC16(dst, src) \
    asm volatile("cp.async.cg.shared.global [%0], [%1], 16;" :: "r"(dst), "l"(src))
#define CP_COMMIT()   asm volatile("cp.async.commit_group;" ::: "memory")
#define CP_WAIT(n)    asm volatile("cp.async.wait_group %0;" :: "n"(n) : "memory")

__device__ __forceinline__ uint32_t smem_u32(const void* p) {
    uint32_t a;
    asm("{ .reg .u64 t; cvta.to.shared.u64 t, %1; cvt.u32.u64 %0, t; }"
        : "=r"(a) : "l"(p));
    return a;
}

__device__ __forceinline__ void ldsm_x4(uint32_t& r0, uint32_t& r1,
                                        uint32_t& r2, uint32_t& r3, uint32_t addr)
{
    asm volatile("ldmatrix.sync.aligned.m8n8.x4.shared.b16 {%0,%1,%2,%3}, [%4];"
        : "=r"(r0), "=r"(r1), "=r"(r2), "=r"(r3) : "r"(addr));
}
__device__ __forceinline__ void ldsm_x4_t(uint32_t& r0, uint32_t& r1,
                                          uint32_t& r2, uint32_t& r3, uint32_t addr)
{
    asm volatile("ldmatrix.sync.aligned.m8n8.x4.trans.shared.b16 {%0,%1,%2,%3}, [%4];"
        : "=r"(r0), "=r"(r1), "=r"(r2), "=r"(r3) : "r"(addr));
}
__device__ __forceinline__ void mma_16816(float* c, const uint32_t* a,
                                          const uint32_t* b)
{
    asm volatile("mma.sync.aligned.m16n8k16.row.col.f32.f16.f16.f32 "
        "{%0,%1,%2,%3}, {%4,%5,%6,%7}, {%8,%9}, {%0,%1,%2,%3};"
        : "+f"(c[0]), "+f"(c[1]), "+f"(c[2]), "+f"(c[3])
        : "r"(a[0]), "r"(a[1]), "r"(a[2]), "r"(a[3]), "r"(b[0]), "r"(b[1]));
}

// --------------------- raw mma.sync GEMM (3-stage ring) --------------------
static constexpr int BM = 128, BN = 128, BK = 64;
static constexpr int A_BYTES = BM * BK * 2;        // 16384
static constexpr int B_BYTES = BK * BN * 2;        // 16384
static constexpr int STAGE   = A_BYTES + B_BYTES;  // 32768
static constexpr int NSTG    = 3;
static constexpr int GEMM_SMEM = NSTG * STAGE;     // 98304

template<int EPI, int OUTH>
__global__ void __launch_bounds__(256, 2)
gemm_mma(const __half* __restrict__ A, const __half* __restrict__ W,
         const float* __restrict__ bias, const float* __restrict__ R,
         void* __restrict__ Cout, int M, int N, int K)
{
    extern __shared__ __align__(128) char smem[];
    uint32_t sA_u[NSTG], sB_u[NSTG];
#pragma unroll
    for (int i = 0; i < NSTG; i++) {
        sA_u[i] = smem_u32(smem + i * STAGE);
        sB_u[i] = smem_u32(smem + i * STAGE + A_BYTES);
    }

    int tid  = threadIdx.x;
    int wid  = tid >> 5;
    int lane = tid & 31;
    int wm   = wid >> 2;
    int wn   = wid & 3;
    int m0   = blockIdx.y * BM;
    int n0   = blockIdx.x * BN;

    float acc[4][4][4];
#pragma unroll
    for (int i = 0; i < 4; i++)
#pragma unroll
        for (int j = 0; j < 4; j++)
#pragma unroll
            for (int r = 0; r < 4; r++) acc[i][j][r] = 0.0f;

    int nk = K / BK;

    // ---- hoisted loader addressing ----
    // i-step adds 32 (A) / 16 (B) rows: multiples of 8 -> swizzle XOR invariant,
    // smem offset advances by exactly 4096 B.
    int ra = tid >> 3, ca = tid & 7;
    int rb = tid >> 4, cb = tid & 15;
    int pb = (cb & 8) | ((cb & 7) ^ (rb & 7));
    uint32_t aDst[NSTG], bDst[NSTG];
#pragma unroll
    for (int i = 0; i < NSTG; i++) {
        aDst[i] = sA_u[i] + (uint32_t)((ra * 8 + (ca ^ (ra & 7))) * 16);
        bDst[i] = sB_u[i] + (uint32_t)((rb * 16 + pb) * 16);
    }
    const __half* aP[4];
    const __half* bP[4];
#pragma unroll
    for (int i = 0; i < 4; i++) {
        aP[i] = A + (size_t)(m0 + ra + 32 * i) * K + ca * 8;
        bP[i] = W + (size_t)(rb + 16 * i) * N + n0 + cb * 8;
    }
    const size_t bstep = (size_t)BK * N;

    auto issue_stage = [&](int buf) {
#pragma unroll
        for (int i = 0; i < 4; i++) {
            CP_ASYNC16(aDst[buf] + i * 4096, aP[i]);
            CP_ASYNC16(bDst[buf] + i * 4096, bP[i]);
        }
        CP_COMMIT();
#pragma unroll
        for (int i = 0; i < 4; i++) { aP[i] += BK; bP[i] += bstep; }
    };

    issue_stage(0);
    issue_stage(1);

    int l15 = lane & 15;
    int hi  = lane >> 4;
    int x   = lane & 7;

    for (int s = 0; s < nk; ++s) {
        int buf = s % NSTG;
        if (s + 1 < nk) { CP_WAIT(1); } else { CP_WAIT(0); }
        __syncthreads();
        if (s + 2 < nk) issue_stage((s + 2) % NSTG);

        uint32_t aT = sA_u[buf];
        uint32_t bT = sB_u[buf];
#pragma unroll
        for (int ks = 0; ks < 4; ++ks) {
            uint32_t a[4][4];
#pragma unroll
            for (int mi = 0; mi < 4; mi++) {
                int row = wm * 64 + mi * 16 + l15;
                int ch  = (ks * 2 + hi) ^ x;
                ldsm_x4(a[mi][0], a[mi][1], a[mi][2], a[mi][3],
                        aT + (uint32_t)((row * 8 + ch) * 16));
            }
            uint32_t b[4][2];
#pragma unroll
            for (int nj = 0; nj < 2; nj++) {
                int row = ks * 16 + l15;
                int cl  = wn * 4 + nj * 2 + hi;
                int ch  = (cl & 8) | ((cl & 7) ^ x);
                uint32_t r0, r1, r2, r3;
                ldsm_x4_t(r0, r1, r2, r3, bT + (uint32_t)((row * 16 + ch) * 16));
                b[nj * 2][0] = r0; b[nj * 2][1] = r1;
                b[nj * 2 + 1][0] = r2; b[nj * 2 + 1][1] = r3;
            }
#pragma unroll
            for (int mi = 0; mi < 4; mi++)
#pragma unroll
                for (int ni = 0; ni < 4; ni++)
                    mma_16816(acc[mi][ni], a[mi], b[ni]);
        }
    }

    int rbase = m0 + wm * 64 + (lane >> 2);
    int cbase = n0 + wn * 32 + (lane & 3) * 2;
#pragma unroll
    for (int mi = 0; mi < 4; mi++) {
#pragma unroll
        for (int ni = 0; ni < 4; ni++) {
            int col = cbase + ni * 8;
            float2 bi = *reinterpret_cast<const float2*>(bias + col);
#pragma unroll
            for (int h = 0; h < 2; h++) {
                int row = rbase + mi * 16 + h * 8;
                float v0 = acc[mi][ni][h * 2 + 0] + bi.x;
                float v1 = acc[mi][ni][h * 2 + 1] + bi.y;
                if (EPI == 1) { v0 = gelu_f(v0); v1 = gelu_f(v1); }
                if (EPI == 2) {
                    float2 rr = *reinterpret_cast<const float2*>(
                        R + (size_t)row * N + col);
                    v0 += rr.x; v1 += rr.y;
                }
                if (OUTH) {
                    __half2 hv = __floats2half2_rn(v0, v1);
                    *reinterpret_cast<__half2*>(
                        (__half*)Cout + (size_t)row * N + col) = hv;
                } else {
                    float2 fv = { v0, v1 };
                    *reinterpret_cast<float2*>(
                        (float*)Cout + (size_t)row * N + col) = fv;
                }
            }
        }
    }
}

// ---------------- raw mma.sync register-resident flash attention -----------
// 256 threads (8 warps), 128 q rows/block, KV tiles 64, double-buffered.
// exp2-domain softmax; hoisted KV loader addressing.
static constexpr int FLASH_SMEM = 16384 + 4 * 8192;   // Q(128x64) + 2*(K,V)

__global__ void __launch_bounds__(256, 2)
flash_mma(const __half* __restrict__ QKV, __half* __restrict__ ATT)
{
    extern __shared__ __align__(128) char smem[];
    uint32_t Qu = smem_u32(smem);
    uint32_t Ku[2] = { Qu + 16384, Qu + 32768 };
    uint32_t Vu[2] = { Qu + 24576, Qu + 40960 };

    int tid  = threadIdx.x;
    int w    = tid >> 5;
    int lane = tid & 31;
    int qt   = gridDim.x - 1 - blockIdx.x;      // heavy tiles first
    int bh   = blockIdx.y;
    int b    = bh >> 4;
    int h    = bh & 15;
    int q0   = qt * 128;

    // ---- hoisted KV loader addressing ----
    int lr = tid >> 3, lc = tid & 7;
    uint32_t ldoff = (uint32_t)((lr * 8 + (lc ^ (lr & 7))) * 16);
    const __half* kP = QKV + (size_t)(b * Tlen + lr) * (3 * Cdim)
                     + Cdim + h * HDim + lc * 8;
    const __half* vP = kP + Cdim;
    const size_t KV_TILE_STEP = (size_t)64 * 3 * Cdim;

    auto ld_kv = [&](int buf) {
#pragma unroll
        for (int i = 0; i < 2; i++) {
            CP_ASYNC16(Ku[buf] + ldoff + i * 4096, kP + (size_t)i * 32 * (3 * Cdim));
            CP_ASYNC16(Vu[buf] + ldoff + i * 4096, vP + (size_t)i * 32 * (3 * Cdim));
        }
        CP_COMMIT();
        kP += KV_TILE_STEP;
        vP += KV_TILE_STEP;
    };

    // Q load (once)
    const __half* Qg = QKV + (size_t)(b * Tlen + q0) * (3 * Cdim) + h * HDim;
#pragma unroll
    for (int i = 0; i < 4; i++) {
        int f = tid + i * 256;
        int r = f >> 3, c = f & 7;
        uint32_t d = Qu + (uint32_t)((r * 8 + (c ^ (r & 7))) * 16);
        CP_ASYNC16(d, Qg + (size_t)r * (3 * Cdim) + c * 8);
    }
    CP_COMMIT();
    ld_kv(0);

    uint32_t qa[4][4];
    {
        CP_WAIT(1);
        __syncthreads();
        int l15_ = lane & 15, hi_ = lane >> 4;
        int row = w * 16 + l15_;
#pragma unroll
        for (int dk = 0; dk < 4; dk++) {
            int ch = (dk * 2 + hi_) ^ (row & 7);
            ldsm_x4(qa[dk][0], qa[dk][1], qa[dk][2], qa[dk][3],
                    Qu + (uint32_t)((row * 8 + ch) * 16));
        }
        const float QSC = 0.18033688f;   // log2(e) * 0.125
        __half2 sc = __floats2half2_rn(QSC, QSC);
#pragma unroll
        for (int dk = 0; dk < 4; dk++)
#pragma unroll
            for (int r = 0; r < 4; r++) {
                __half2 v = *reinterpret_cast<__half2*>(&qa[dk][r]);
                v = __hmul2(v, sc);
                qa[dk][r] = *reinterpret_cast<uint32_t*>(&v);
            }
    }

    float o[8][4];
#pragma unroll
    for (int n = 0; n < 8; n++)
#pragma unroll
        for (int r = 0; r < 4; r++) o[n][r] = 0.0f;
    float m0 = -1e30f, m1 = -1e30f, l0 = 0.0f, l1 = 0.0f;

    int g    = lane >> 3;
    int r8   = lane & 7;
    int l15  = lane & 15;
    int hi   = lane >> 4;
    int qr   = q0 + w * 16 + (lane >> 2);
    int ntm1 = q0 >> 6;
    int nt   = ntm1 + 1;

    for (int t = 0; t <= nt; ++t) {
        int buf = t & 1;
        if (t < nt) {
            ld_kv(buf ^ 1);
            CP_WAIT(1);
        } else {
            CP_WAIT(0);
        }
        __syncthreads();

        float s[8][4];
#pragma unroll
        for (int n = 0; n < 8; n++)
#pragma unroll
            for (int r = 0; r < 4; r++) s[n][r] = 0.0f;
#pragma unroll
        for (int dk = 0; dk < 4; dk++) {
            uint32_t kb[8][2];
#pragma unroll
            for (int p = 0; p < 4; p++) {
                int row = p * 16 + (g >> 1) * 8 + r8;
                int ch  = (dk * 2 + (g & 1)) ^ (row & 7);
                uint32_t r0, r1, r2, r3;
                ldsm_x4(r0, r1, r2, r3, Ku[buf] + (uint32_t)((row * 8 + ch) * 16));
                kb[2*p][0] = r0; kb[2*p][1] = r1;
                kb[2*p+1][0] = r2; kb[2*p+1][1] = r3;
            }
#pragma unroll
            for (int n = 0; n < 8; n++) mma_16816(s[n], qa[dk], kb[n]);
        }

        bool needmask = (t >= ntm1);
        float mx0 = -1e30f, mx1 = -1e30f;
#pragma unroll
        for (int n = 0; n < 8; n++) {
            if (needmask) {
                int col = t * 64 + n * 8 + (lane & 3) * 2;
                if (col     > qr)     s[n][0] = -1e30f;
                if (col + 1 > qr)     s[n][1] = -1e30f;
                if (col     > qr + 8) s[n][2] = -1e30f;
                if (col + 1 > qr + 8) s[n][3] = -1e30f;
            }
            mx0 = fmaxf(mx0, fmaxf(s[n][0], s[n][1]));
            mx1 = fmaxf(mx1, fmaxf(s[n][2], s[n][3]));
        }
        mx0 = fmaxf(mx0, __shfl_xor_sync(0xFFFFFFFFu, mx0, 1));
        mx0 = fmaxf(mx0, __shfl_xor_sync(0xFFFFFFFFu, mx0, 2));
        mx1 = fmaxf(mx1, __shfl_xor_sync(0xFFFFFFFFu, mx1, 1));
        mx1 = fmaxf(mx1, __shfl_xor_sync(0xFFFFFFFFu, mx1, 2));

        float mn0 = fmaxf(m0, mx0), mn1 = fmaxf(m1, mx1);
        float sc0 = exp2f(m0 - mn0), sc1 = exp2f(m1 - mn1);
        float sum0 = 0.0f, sum1 = 0.0f;
        uint32_t pa[4][4];
#pragma unroll
        for (int dk = 0; dk < 4; dk++) {
            float e00 = exp2f(s[2*dk][0]   - mn0);
            float e01 = exp2f(s[2*dk][1]   - mn0);
            float e02 = exp2f(s[2*dk][2]   - mn1);
            float e03 = exp2f(s[2*dk][3]   - mn1);
            float e10 = exp2f(s[2*dk+1][0] - mn0);
            float e11 = exp2f(s[2*dk+1][1] - mn0);
            float e12 = exp2f(s[2*dk+1][2] - mn1);
            float e13 = exp2f(s[2*dk+1][3] - mn1);
            sum0 += e00 + e01 + e10 + e11;
            sum1 += e02 + e03 + e12 + e13;
            __half2 h0 = __floats2half2_rn(e00, e01);
            __half2 h1 = __floats2half2_rn(e02, e03);
            __half2 h2 = __floats2half2_rn(e10, e11);
            __half2 h3 = __floats2half2_rn(e12, e13);
            pa[dk][0] = *reinterpret_cast<uint32_t*>(&h0);
            pa[dk][1] = *reinterpret_cast<uint32_t*>(&h1);
            pa[dk][2] = *reinterpret_cast<uint32_t*>(&h2);
            pa[dk][3] = *reinterpret_cast<uint32_t*>(&h3);
        }
        sum0 += __shfl_xor_sync(0xFFFFFFFFu, sum0, 1);
        sum0 += __shfl_xor_sync(0xFFFFFFFFu, sum0, 2);
        sum1 += __shfl_xor_sync(0xFFFFFFFFu, sum1, 1);
        sum1 += __shfl_xor_sync(0xFFFFFFFFu, sum1, 2);
        l0 = l0 * sc0 + sum0;
        l1 = l1 * sc1 + sum1;
        m0 = mn0; m1 = mn1;
#pragma unroll
        for (int n = 0; n < 8; n++) {
            o[n][0] *= sc0; o[n][1] *= sc0;
            o[n][2] *= sc1; o[n][3] *= sc1;
        }

#pragma unroll
        for (int dk = 0; dk < 4; dk++) {
            uint32_t vb[8][2];
            int row = dk * 16 + l15;
#pragma unroll
            for (int p = 0; p < 4; p++) {
                int ch = (p * 2 + hi) ^ (row & 7);
                uint32_t r0, r1, r2, r3;
                ldsm_x4_t(r0, r1, r2, r3, Vu[buf] + (uint32_t)((row * 8 + ch) * 16));
                vb[2*p][0] = r0; vb[2*p][1] = r1;
                vb[2*p+1][0] = r2; vb[2*p+1][1] = r3;
            }
#pragma unroll
            for (int n = 0; n < 8; n++) mma_16816(o[n], pa[dk], vb[n]);
        }
        __syncthreads();
    }

    float inv0 = 1.0f / l0, inv1 = 1.0f / l1;
    int row0 = q0 + w * 16 + (lane >> 2);
    __half* base = ATT + (size_t)(b * Tlen) * Cdim + h * HDim;
#pragma unroll
    for (int n = 0; n < 8; n++) {
        int col = n * 8 + (lane & 3) * 2;
        __half2 h0 = __floats2half2_rn(o[n][0] * inv0, o[n][1] * inv0);
        __half2 h1 = __floats2half2_rn(o[n][2] * inv1, o[n][3] * inv1);
        *reinterpret_cast<__half2*>(base + (size_t)row0 * Cdim + col) = h0;
        *reinterpret_cast<__half2*>(base + (size_t)(row0 + 8) * Cdim + col) = h1;
    }
}

// -------------------------------- launcher ---------------------------------
extern "C" void kernel_launch(void* const* d_in, const int* in_sizes, int n_in,
                              void* d_out, int out_size)
{
    const float* x           = (const float*)d_in[0];
    const float* ln1_g       = (const float*)d_in[1];
    const float* ln1_b       = (const float*)d_in[2];
    const float* w_qkv       = (const float*)d_in[3];
    const float* b_qkv       = (const float*)d_in[4];
    const float* w_attn_proj = (const float*)d_in[5];
    const float* b_attn_proj = (const float*)d_in[6];
    const float* ln2_g       = (const float*)d_in[7];
    const float* ln2_b       = (const float*)d_in[8];
    const float* w_fc        = (const float*)d_in[9];
    const float* b_fc        = (const float*)d_in[10];
    const float* w_mlp_proj  = (const float*)d_in[11];
    const float* b_mlp_proj  = (const float*)d_in[12];
    float* out = (float*)d_out;

    float *X1;
    __half *H16, *QKV16, *ATT16, *FF16, *Wq16, *Wa16, *Wf16, *Wm16;
    cudaGetSymbolAddress((void**)&X1,    g_X1);
    cudaGetSymbolAddress((void**)&H16,   g_H16);
    cudaGetSymbolAddress((void**)&QKV16, g_QKV16);
    cudaGetSymbolAddress((void**)&ATT16, g_ATT16);
    cudaGetSymbolAddress((void**)&FF16,  g_FF16);
    cudaGetSymbolAddress((void**)&Wq16,  g_Wq16);
    cudaGetSymbolAddress((void**)&Wa16,  g_Wa16);
    cudaGetSymbolAddress((void**)&Wf16,  g_Wf16);
    cudaGetSymbolAddress((void**)&Wm16,  g_Wm16);

    cudaFuncSetAttribute(gemm_mma<0,1>, cudaFuncAttributeMaxDynamicSharedMemorySize, GEMM_SMEM);
    cudaFuncSetAttribute(gemm_mma<1,1>, cudaFuncAttributeMaxDynamicSharedMemorySize, GEMM_SMEM);
    cudaFuncSetAttribute(gemm_mma<2,0>, cudaFuncAttributeMaxDynamicSharedMemorySize, GEMM_SMEM);
    cudaFuncSetAttribute(flash_mma, cudaFuncAttributeMaxDynamicSharedMemorySize, FLASH_SMEM);

    // weight conversion (single launch)
    {
        int total4 = (3 * Cdim * Cdim + Cdim * Cdim + Cdim * FFdim + FFdim * Cdim) / 4;
        cvt_all_kernel<<<(total4 + 255) / 256, 256>>>(
            w_qkv, w_attn_proj, w_fc, w_mlp_proj, Wq16, Wa16, Wf16, Wm16);
    }

    // 1. h = LN1(x)                      (fp16 out)
    ln_kernel<<<Mrows / 8, 256>>>(x, ln1_g, ln1_b, H16);
    // 2. qkv = h @ w_qkv + b             (fp16 out)
    gemm_mma<0,1><<<dim3(3 * Cdim / BN, Mrows / BM), 256, GEMM_SMEM>>>(
        H16, Wq16, b_qkv, nullptr, QKV16, Mrows, 3 * Cdim, Cdim);
    // 3. causal flash attention (raw mma) (fp16 out)
    flash_mma<<<dim3(Tlen / 128, Bsz * NHead), 256, FLASH_SMEM>>>(QKV16, ATT16);
    // 4. x1 = x + attn @ w_attn_proj + b (fp32 out)
    gemm_mma<2,0><<<dim3(Cdim / BN, Mrows / BM), 256, GEMM_SMEM>>>(
        ATT16, Wa16, b_attn_proj, x, X1, Mrows, Cdim, Cdim);
    // 5. h = LN2(x1)                     (fp16 out)
    ln_kernel<<<Mrows / 8, 256>>>(X1, ln2_g, ln2_b, H16);
    // 6. ff = gelu(h @ w_fc + b)         (fp16 out)
    gemm_mma<1,1><<<dim3(FFdim / BN, Mrows / BM), 256, GEMM_SMEM>>>(
        H16, Wf16, b_fc, nullptr, FF16, Mrows, FFdim, Cdim);
    // 7. out = x1 + ff @ w_mlp_proj + b  (fp32 out)
    gemm_mma<2,0><<<dim3(Cdim / BN, Mrows / BM), 256, GEMM_SMEM>>>(
        FF16, Wm16, b_mlp_proj, X1, out, Mrows, Cdim, FFdim);
}